// round 16
// baseline (speedup 1.0000x reference)
#include <cuda_runtime.h>
#include <cuda_fp16.h>
#include <cstdint>

// ---------------------------------------------------------------------------
// GAE 4-layer GCN autoencoder: algebraic fusion + fp16 pipeline + fp16 mma.
// This round: persistent megakernel for all 4 aggregation passes (software
// grid barriers), X pre-converted to half on a 3rd stream, z off-path.
// ---------------------------------------------------------------------------

#define N_NODES 20000
#define IN_DIM  1024
#define HID_DIM 512
#define OUT_DIM 128
#define N_EDGES 160000
#define AGG_CTAS 592   // 4 per SM (148 SMs; GB300 has 152 -> safe)

__device__ alignas(16) __half g_Xh[(size_t)N_NODES * IN_DIM];       // X half
__device__ alignas(16) __half g_Th[(size_t)N_NODES * OUT_DIM];      // P / S2
__device__ alignas(16) __half g_Hh[(size_t)N_NODES * OUT_DIM];      // S1 / R
__device__ alignas(16) __half g_Zh[(size_t)N_NODES * OUT_DIM];      // h2 half copy
__device__ alignas(16) float  g_W21[(size_t)OUT_DIM * IN_DIM];      // fp32 (for hw21)
__device__ alignas(16) __half g_W21h[(size_t)OUT_DIM * IN_DIM];     // [128,1024] n-major
__device__ alignas(16) __half g_HW21th[(size_t)IN_DIM * OUT_DIM];   // [1024,128] n-major
__device__ alignas(16) __half g_Hth[(size_t)OUT_DIM * OUT_DIM];     // head1^T
__device__ alignas(16) float  g_u2[OUT_DIM];
__device__ alignas(16) float  g_u4[IN_DIM];
__device__ float g_dinv[N_NODES];
__device__ float g_sn[N_NODES];
__device__ float g_c[N_NODES];
__device__ int   g_cnt[N_NODES];     // invariant: zero at kernel_launch entry
__device__ int   g_off[N_NODES + 1];
__device__ int   g_cur[N_NODES];
__device__ int2  g_adj[N_EDGES];
__device__ unsigned g_barc[3];       // grid-barrier counters; zeroed by k_scan

// half buffer selectors: 1 g_Th, 2 g_Hh, 3 g_Zh
template <int SEL>
__device__ __forceinline__ const __half* pickhb() {
    if (SEL == 1) return g_Th;
    if (SEL == 2) return g_Hh;
    return g_Zh;
}
template <int SEL>
__device__ __forceinline__ __half* pickhbw() {
    if (SEL == 1) return g_Th;
    if (SEL == 2) return g_Hh;
    return g_Zh;
}
// mma B selectors: 3 g_W21h, 4 g_HW21th, 5 g_Hth
template <int SEL>
__device__ __forceinline__ const __half* pickB() {
    if (SEL == 3) return g_W21h;
    if (SEL == 4) return g_HW21th;
    return g_Hth;
}

__device__ __forceinline__ float4 h4f(uint2 r) {
    __half2 a = *(__half2*)&r.x, b = *(__half2*)&r.y;
    float2 f0 = __half22float2(a), f1 = __half22float2(b);
    return make_float4(f0.x, f0.y, f1.x, f1.y);
}
__device__ __forceinline__ uint2 f4h(float4 v) {
    __half2 a = __floats2half2_rn(v.x, v.y);
    __half2 b = __floats2half2_rn(v.z, v.w);
    uint2 r;
    r.x = *(unsigned*)&a; r.y = *(unsigned*)&b;
    return r;
}

// int64 detection (int64 idx < 2^31 -> odd int32 words zero)
__device__ __forceinline__ int probe64(const int* __restrict__ ei32) {
    return (ei32[1] == 0) & (ei32[3] == 0) & (ei32[5] == 0) &
           (ei32[7] == 0) & (ei32[9] == 0) & (ei32[11] == 0);
}
__device__ __forceinline__ int load_idx64(const void* ei, int is64, int e_cnt,
                                          int row, int e) {
    if (is64) return (int)((const long long*)ei)[(size_t)row * e_cnt + e];
    return ((const int*)ei)[(size_t)row * e_cnt + e];
}

// ---------------------------------------------------------------------------
// X -> half (streaming convert; 8 floats per thread)
// ---------------------------------------------------------------------------
__global__ void k_xh(const float* __restrict__ X, int total8) {
    int i = blockIdx.x * blockDim.x + threadIdx.x;
    if (i < total8) {
        float4 a = ((const float4*)X)[(size_t)i * 2];
        float4 b = ((const float4*)X)[(size_t)i * 2 + 1];
        uint4 o;
        __half2 h;
        h = __floats2half2_rn(a.x, a.y); o.x = *(unsigned*)&h;
        h = __floats2half2_rn(a.z, a.w); o.y = *(unsigned*)&h;
        h = __floats2half2_rn(b.x, b.y); o.z = *(unsigned*)&h;
        h = __floats2half2_rn(b.z, b.w); o.w = *(unsigned*)&h;
        *(uint4*)(g_Xh + (size_t)i * 8) = o;
    }
}

// ---------------------------------------------------------------------------
// CSR: count (g_cnt zero at entry; k_scan restores it)
// ---------------------------------------------------------------------------
__global__ void k_count(const void* __restrict__ ei, int e_cnt, int n) {
    int e = blockIdx.x * blockDim.x + threadIdx.x;
    int is64 = probe64((const int*)ei);
    if (e < e_cnt) {
        int d = load_idx64(ei, is64, e_cnt, 1, e);
        if ((unsigned)d < (unsigned)n) atomicAdd(&g_cnt[d], 1);
    }
}

// ---------------------------------------------------------------------------
// Single-pass scan (+ dinv/sn); re-zeros g_cnt and g_barc for this call.
// ---------------------------------------------------------------------------
#define SCAN_CHUNK ((N_NODES + 1023) / 1024)

__global__ __launch_bounds__(1024)
void k_scan(int n) {
    int tid = threadIdx.x;
    int lane = tid & 31, wid = tid >> 5;
    if (tid < 3) g_barc[tid] = 0;
    int base = tid * SCAN_CHUNK;
    int vloc[SCAN_CHUNK];
    int s = 0;
#pragma unroll
    for (int j = 0; j < SCAN_CHUNK; j++) {
        int i = base + j;
        int v = (i < n) ? g_cnt[i] : 0;
        vloc[j] = v;
        s += v;
    }
    int x = s;
#pragma unroll
    for (int d = 1; d < 32; d <<= 1) {
        int y = __shfl_up_sync(0xFFFFFFFFu, x, d);
        if (lane >= d) x += y;
    }
    __shared__ int ws[32];
    if (lane == 31) ws[wid] = x;
    __syncthreads();
    if (wid == 0) {
        int w = ws[lane];
#pragma unroll
        for (int d = 1; d < 32; d <<= 1) {
            int y = __shfl_up_sync(0xFFFFFFFFu, w, d);
            if (lane >= d) w += y;
        }
        ws[lane] = w;
    }
    __syncthreads();
    int excl = x - s + ((wid > 0) ? ws[wid - 1] : 0);
    if (tid == 0) g_off[0] = 0;
#pragma unroll
    for (int j = 0; j < SCAN_CHUNK; j++) {
        int i = base + j;
        if (i < n) {
            g_cur[i] = excl;
            excl += vloc[j];
            g_off[i + 1] = excl;
            float r = rsqrtf((float)(vloc[j] + 1));
            g_dinv[i] = r;
            g_sn[i] = r * r;
            g_cnt[i] = 0;
        }
    }
}

__global__ void k_fill(const void* __restrict__ ei, int e_cnt, int n) {
    int e = blockIdx.x * blockDim.x + threadIdx.x;
    int is64 = probe64((const int*)ei);
    if (e < e_cnt) {
        int s = load_idx64(ei, is64, e_cnt, 0, e);
        int d = load_idx64(ei, is64, e_cnt, 1, e);
        if ((unsigned)s >= (unsigned)n) s = 0;
        if ((unsigned)d >= (unsigned)n) d = 0;
        float w = g_dinv[s] * g_dinv[d];
        int pos = atomicAdd(&g_cur[d], 1);
        g_adj[pos] = make_int2(s, __float_as_int(w));
    }
}

// ---------------------------------------------------------------------------
// misc: u4 (blocks 0..15), u2 (block 16), Hth (block 17)
// ---------------------------------------------------------------------------
__global__ void k_misc(const float* __restrict__ W1, const float* __restrict__ W2,
                       const float* __restrict__ b1, const float* __restrict__ b3,
                       const float* __restrict__ head1) {
    int b = blockIdx.x;
    __shared__ float red[256];
    if (b < 16) {
        int fl = threadIdx.x & 63;
        int kg = threadIdx.x >> 6;
        int f = b * 64 + fl;
        float s = 0.f;
        for (int k = kg * 128; k < kg * 128 + 128; k++)
            s += b3[k] * W1[(size_t)k * IN_DIM + f];
        red[threadIdx.x] = s;
        __syncthreads();
        if (threadIdx.x < 64)
            g_u4[b * 64 + threadIdx.x] = red[threadIdx.x] + red[64 + threadIdx.x] +
                                         red[128 + threadIdx.x] + red[192 + threadIdx.x];
    } else if (b == 16) {
        int o = threadIdx.x & 127;
        int kg = threadIdx.x >> 7;
        float s = 0.f;
        for (int k = kg * 256; k < kg * 256 + 256; k++)
            s += W2[(size_t)o * HID_DIM + k] * b1[k];
        red[threadIdx.x] = s;
        __syncthreads();
        if (threadIdx.x < 128)
            g_u2[threadIdx.x] = red[threadIdx.x] + red[128 + threadIdx.x];
    } else {
        for (int idx = threadIdx.x; idx < OUT_DIM * OUT_DIM; idx += 256) {
            int r = idx >> 7, c = idx & 127;
            g_Hth[(size_t)c * OUT_DIM + r] = __float2half(head1[idx]);
        }
    }
}

// ---------------------------------------------------------------------------
// W21 = W2 @ W1 (fp32 FFMA, K=512) -> g_W21 fp32 + g_W21h half.
// grid (IN_DIM/128, 4), BM=32.
// ---------------------------------------------------------------------------
__global__ __launch_bounds__(256)
void k_w21(const float* __restrict__ A, const float* __restrict__ B) {
    __shared__ float As[8][32];
    __shared__ float Bs[8][128];
    const int bx = blockIdx.x;
    const int by = blockIdx.y;
    const int tid = threadIdx.x;
    const int tcol = tid % 16;
    const int trow = tid / 16;

    float acc[2][8];
#pragma unroll
    for (int i = 0; i < 2; i++)
#pragma unroll
        for (int j = 0; j < 8; j++) acc[i][j] = 0.0f;

    for (int k0 = 0; k0 < HID_DIM; k0 += 8) {
        if (tid < 64) {
            int aRow = tid >> 1;
            int aCol = (tid & 1) << 2;
            int m = by * 32 + aRow;
            float4 av = *(const float4*)(A + (size_t)m * HID_DIM + k0 + aCol);
            As[aCol + 0][aRow] = av.x;
            As[aCol + 1][aRow] = av.y;
            As[aCol + 2][aRow] = av.z;
            As[aCol + 3][aRow] = av.w;
        }
        {
            int kk = tid >> 5;
            int nn = (tid & 31) << 2;
            float4 bv = *(const float4*)(B + (size_t)(k0 + kk) * IN_DIM + bx * 128 + nn);
            *(float4*)&Bs[kk][nn] = bv;
        }
        __syncthreads();
#pragma unroll
        for (int k = 0; k < 8; k++) {
            float ra[2], rb[8];
#pragma unroll
            for (int i = 0; i < 2; i++) ra[i] = As[k][trow * 2 + i];
#pragma unroll
            for (int j = 0; j < 8; j++) rb[j] = Bs[k][tcol * 8 + j];
#pragma unroll
            for (int i = 0; i < 2; i++)
#pragma unroll
                for (int j = 0; j < 8; j++) acc[i][j] += ra[i] * rb[j];
        }
        __syncthreads();
    }
#pragma unroll
    for (int i = 0; i < 2; i++) {
        int m = by * 32 + trow * 2 + i;
#pragma unroll
        for (int j = 0; j < 8; j++) {
            int col = bx * 128 + tcol * 8 + j;
            g_W21[(size_t)m * IN_DIM + col]  = acc[i][j];
            g_W21h[(size_t)m * IN_DIM + col] = __float2half(acc[i][j]);
        }
    }
}

// ---------------------------------------------------------------------------
// HW21 = head1 @ W21 (fp32 FFMA, K=128) -> g_HW21th half transposed.
// grid (IN_DIM/128, 4), BM=32.
// ---------------------------------------------------------------------------
__global__ __launch_bounds__(256)
void k_hw21(const float* __restrict__ head1) {
    __shared__ float As[8][32];
    __shared__ float Bs[8][128];
    const int bx = blockIdx.x;
    const int by = blockIdx.y;
    const int tid = threadIdx.x;
    const int tcol = tid % 16;
    const int trow = tid / 16;

    float acc[2][8];
#pragma unroll
    for (int i = 0; i < 2; i++)
#pragma unroll
        for (int j = 0; j < 8; j++) acc[i][j] = 0.0f;

    for (int k0 = 0; k0 < OUT_DIM; k0 += 8) {
        if (tid < 64) {
            int aRow = tid >> 1;
            int aCol = (tid & 1) << 2;
            int m = by * 32 + aRow;
            float4 av = *(const float4*)(head1 + (size_t)m * OUT_DIM + k0 + aCol);
            As[aCol + 0][aRow] = av.x;
            As[aCol + 1][aRow] = av.y;
            As[aCol + 2][aRow] = av.z;
            As[aCol + 3][aRow] = av.w;
        }
        {
            int kk = tid >> 5;
            int nn = (tid & 31) << 2;
            float4 bv = *(const float4*)(g_W21 + (size_t)(k0 + kk) * IN_DIM + bx * 128 + nn);
            *(float4*)&Bs[kk][nn] = bv;
        }
        __syncthreads();
#pragma unroll
        for (int k = 0; k < 8; k++) {
            float ra[2], rb[8];
#pragma unroll
            for (int i = 0; i < 2; i++) ra[i] = As[k][trow * 2 + i];
#pragma unroll
            for (int j = 0; j < 8; j++) rb[j] = Bs[k][tcol * 8 + j];
#pragma unroll
            for (int i = 0; i < 2; i++)
#pragma unroll
                for (int j = 0; j < 8; j++) acc[i][j] += ra[i] * rb[j];
        }
        __syncthreads();
    }
#pragma unroll
    for (int i = 0; i < 2; i++) {
        int m = by * 32 + trow * 2 + i;
#pragma unroll
        for (int j = 0; j < 8; j++) {
            int col = bx * 128 + tcol * 8 + j;
            g_HW21th[(size_t)col * OUT_DIM + m] = __float2half(acc[i][j]);
        }
    }
}

// ---------------------------------------------------------------------------
// fp16 tensor-core GEMM (TN form), m16n8k16, register-prefetch pipelined.
//   AMODE: 1 = g_Zh, 2 = g_Hh, 4 = g_Xh (all half A).
//   CH: 1 -> C = g_Th (half); 0 -> C = Cext fp32.
// ---------------------------------------------------------------------------
template <int AMODE, int BSEL, int CH, int CORR4, int BMv>
__global__ __launch_bounds__(256)
void k_mma(int M, int Nn, int K,
           float* __restrict__ Cext,
           const float* __restrict__ bias) {
    constexpr int MT = BMv / 32;
    constexpr int ARH = (BMv + 63) / 64;
    const __half* B = pickB<BSEL>();
    const __half* Ah = (AMODE == 1) ? g_Zh : (AMODE == 2) ? g_Hh : g_Xh;

    __shared__ __half As[BMv][40];
    __shared__ __half Bs[128][40];

    const int tid  = threadIdx.x;
    const int lane = tid & 31;
    const int wid  = tid >> 5;
    const int g    = lane >> 2;
    const int t    = lane & 3;
    const int wm   = (wid & 1) * (BMv / 2);
    const int wn   = (wid >> 1) * 32;
    const int bx   = blockIdx.x;
    const int by   = blockIdx.y;

    uint4 arh[ARH];
    uint4 br4[2];

    auto loadA = [&](int k0) {
#pragma unroll
        for (int i = 0; i < ARH; i++) {
            int u  = tid + i * 256;
            int m  = u >> 2;
            int kq = (u & 3) << 3;
            int gm = by * BMv + m;
            arh[i] = (gm < M) ? *(const uint4*)(Ah + (size_t)gm * K + k0 + kq)
                              : make_uint4(0, 0, 0, 0);
        }
    };
    auto loadB = [&](int k0) {
#pragma unroll
        for (int i = 0; i < 2; i++) {
            int f4 = tid + i * 256;
            int nn = f4 >> 2;
            int kq = (f4 & 3) << 3;
            br4[i] = *(const uint4*)(B + (size_t)(bx * 128 + nn) * K + k0 + kq);
        }
    };
    auto storeA = [&]() {
#pragma unroll
        for (int i = 0; i < ARH; i++) {
            int u  = tid + i * 256;
            int m  = u >> 2;
            int kq = (u & 3) << 3;
            *(uint4*)&As[m][kq] = arh[i];
        }
    };
    auto storeB = [&]() {
#pragma unroll
        for (int i = 0; i < 2; i++) {
            int f4 = tid + i * 256;
            int nn = f4 >> 2;
            int kq = (f4 & 3) << 3;
            *(uint4*)&Bs[nn][kq] = br4[i];
        }
    };

    float c[MT][4][4];
#pragma unroll
    for (int i = 0; i < MT; i++)
#pragma unroll
        for (int j = 0; j < 4; j++)
#pragma unroll
            for (int r = 0; r < 4; r++) c[i][j][r] = 0.0f;

    const int nt = K / 32;
    loadA(0); loadB(0);
    storeA(); storeB();
    __syncthreads();

    for (int it = 0; it < nt; it++) {
        if (it + 1 < nt) { loadA((it + 1) * 32); loadB((it + 1) * 32); }

#pragma unroll
        for (int ks = 0; ks < 2; ks++) {
            unsigned a[MT][4], b[4][2];
            int kb = ks * 16 + 2 * t;
#pragma unroll
            for (int i = 0; i < MT; i++) {
                int mr = wm + i * 16 + g;
                a[i][0] = *(const unsigned*)&As[mr    ][kb    ];
                a[i][1] = *(const unsigned*)&As[mr + 8][kb    ];
                a[i][2] = *(const unsigned*)&As[mr    ][kb + 8];
                a[i][3] = *(const unsigned*)&As[mr + 8][kb + 8];
            }
#pragma unroll
            for (int j = 0; j < 4; j++) {
                int nr = wn + j * 8 + g;
                b[j][0] = *(const unsigned*)&Bs[nr][kb    ];
                b[j][1] = *(const unsigned*)&Bs[nr][kb + 8];
            }
#pragma unroll
            for (int i = 0; i < MT; i++)
#pragma unroll
                for (int j = 0; j < 4; j++) {
                    asm volatile(
                        "mma.sync.aligned.m16n8k16.row.col.f32.f16.f16.f32 "
                        "{%0,%1,%2,%3}, {%4,%5,%6,%7}, {%8,%9}, {%0,%1,%2,%3};"
                        : "+f"(c[i][j][0]), "+f"(c[i][j][1]),
                          "+f"(c[i][j][2]), "+f"(c[i][j][3])
                        : "r"(a[i][0]), "r"(a[i][1]), "r"(a[i][2]), "r"(a[i][3]),
                          "r"(b[j][0]), "r"(b[j][1]));
                }
        }
        __syncthreads();
        if (it + 1 < nt) {
            storeA(); storeB();
            __syncthreads();
        }
    }

#pragma unroll
    for (int j = 0; j < 4; j++) {
        int cn = bx * 128 + wn + j * 8 + t * 2;
        float e0 = bias ? bias[cn]     : 0.0f;
        float e1 = bias ? bias[cn + 1] : 0.0f;
        float u40 = CORR4 ? g_u4[cn]     : 0.0f;
        float u41 = CORR4 ? g_u4[cn + 1] : 0.0f;
#pragma unroll
        for (int i = 0; i < MT; i++) {
            int r0 = by * BMv + wm + i * 16 + g;
            if (r0 < M) {
                float a0 = c[i][j][0] + e0, a1 = c[i][j][1] + e1;
                if (CORR4) { float ci = g_c[r0]; a0 += ci * u40; a1 += ci * u41; }
                if (CH) {
                    __half2 h = __floats2half2_rn(a0, a1);
                    *(__half2*)(g_Th + (size_t)r0 * Nn + cn) = h;
                } else {
                    *(float2*)(Cext + (size_t)r0 * Nn + cn) = make_float2(a0, a1);
                }
            }
            int r1 = r0 + 8;
            if (r1 < M) {
                float a2 = c[i][j][2] + e0, a3 = c[i][j][3] + e1;
                if (CORR4) { float ci = g_c[r1]; a2 += ci * u40; a3 += ci * u41; }
                if (CH) {
                    __half2 h = __floats2half2_rn(a2, a3);
                    *(__half2*)(g_Th + (size_t)r1 * Nn + cn) = h;
                } else {
                    *(float2*)(Cext + (size_t)r1 * Nn + cn) = make_float2(a2, a3);
                }
            }
        }
    }
}

// ---------------------------------------------------------------------------
// Aggregation pass body (persistent loop over nodes), half src, fp32 accum.
// ---------------------------------------------------------------------------
template <int SMODE, int DMODE, int CORR, int WRC>
__device__ __forceinline__ void agg_body(float* __restrict__ Dext,
                                         const float* __restrict__ b,
                                         int n, int gw0, int stride, int lane) {
    const __half* S = pickhb<SMODE>();
    int lo = lane * 4;
    for (int gw = gw0; gw < n; gw += stride) {
        int beg = g_off[gw];
        int end = g_off[gw + 1];
        float sn = g_sn[gw];
        float4 v = h4f(*(const uint2*)(S + (size_t)gw * OUT_DIM + lo));
        float4 acc = make_float4(sn * v.x, sn * v.y, sn * v.z, sn * v.w);
        float cacc = sn;

        int p = beg;
        for (; p + 8 <= end; p += 8) {
            int2  ee[8];
            uint2 uu[8];
#pragma unroll
            for (int q = 0; q < 8; q++) ee[q] = g_adj[p + q];
#pragma unroll
            for (int q = 0; q < 8; q++)
                uu[q] = *(const uint2*)(S + (size_t)ee[q].x * OUT_DIM + lo);
#pragma unroll
            for (int q = 0; q < 8; q++) {
                float w = __int_as_float(ee[q].y);
                if (WRC) cacc += w;
                float4 u = h4f(uu[q]);
                acc.x += w * u.x; acc.y += w * u.y;
                acc.z += w * u.z; acc.w += w * u.w;
            }
        }
        for (; p + 4 <= end; p += 4) {
            int2  ee[4];
            uint2 uu[4];
#pragma unroll
            for (int q = 0; q < 4; q++) ee[q] = g_adj[p + q];
#pragma unroll
            for (int q = 0; q < 4; q++)
                uu[q] = *(const uint2*)(S + (size_t)ee[q].x * OUT_DIM + lo);
#pragma unroll
            for (int q = 0; q < 4; q++) {
                float w = __int_as_float(ee[q].y);
                if (WRC) cacc += w;
                float4 u = h4f(uu[q]);
                acc.x += w * u.x; acc.y += w * u.y;
                acc.z += w * u.z; acc.w += w * u.w;
            }
        }
        for (; p < end; p++) {
            int2 pr = g_adj[p];
            float w = __int_as_float(pr.y);
            if (WRC) cacc += w;
            float4 u = h4f(*(const uint2*)(S + (size_t)pr.x * OUT_DIM + lo));
            acc.x += w * u.x; acc.y += w * u.y;
            acc.z += w * u.z; acc.w += w * u.w;
        }

        if (WRC && lane == 0) g_c[gw] = cacc;

        if (CORR) {
            float ci = g_c[gw];
            acc.x += ci * g_u2[lo + 0] + b[lo + 0];
            acc.y += ci * g_u2[lo + 1] + b[lo + 1];
            acc.z += ci * g_u2[lo + 2] + b[lo + 2];
            acc.w += ci * g_u2[lo + 3] + b[lo + 3];
        }

        if (DMODE == 0) {
            *(float4*)(Dext + (size_t)gw * OUT_DIM + lo) = acc;
            *(uint2*)(g_Zh + (size_t)gw * OUT_DIM + lo) = f4h(acc);
        } else {
            __half* D = pickhbw<DMODE>();
            *(uint2*)(D + (size_t)gw * OUT_DIM + lo) = f4h(acc);
        }
    }
}

// software grid barrier (counters zeroed by k_scan earlier in this launch)
__device__ __forceinline__ void grid_bar(int idx, unsigned nb) {
    __syncthreads();
    if (threadIdx.x == 0) {
        __threadfence();
        unsigned old = atomicAdd(&g_barc[idx], 1u);
        if (old + 1u < nb) {
            while (*(volatile unsigned*)&g_barc[idx] < nb) { }
        }
        __threadfence();
    }
    __syncthreads();
}

// ---------------------------------------------------------------------------
// Megakernel: all 4 aggregation passes with 3 internal grid barriers.
//   pass1: S1 = Ahat P        (g_Th -> g_Hh), computes g_c
//   pass2: h2 = Ahat S1 + ... (g_Hh -> h2_out fp32 + g_Zh)
//   pass3: S2 = Ahat h2       (g_Zh -> g_Th)
//   pass4: R  = Ahat S2       (g_Th -> g_Hh)
// ---------------------------------------------------------------------------
__global__ __launch_bounds__(256, 4)
void k_megagg(float* __restrict__ h2_out, const float* __restrict__ b2, int n) {
    const int lane = threadIdx.x & 31;
    const int gw0 = (blockIdx.x * 256 + threadIdx.x) >> 5;
    const int stride = gridDim.x * 8;
    const unsigned nb = gridDim.x;

    agg_body<1, 2, 0, 1>(nullptr, nullptr, n, gw0, stride, lane);
    grid_bar(0, nb);
    agg_body<2, 0, 1, 0>(h2_out, b2, n, gw0, stride, lane);
    grid_bar(1, nb);
    agg_body<3, 1, 0, 0>(nullptr, nullptr, n, gw0, stride, lane);
    grid_bar(2, nb);
    agg_body<1, 2, 0, 0>(nullptr, nullptr, n, gw0, stride, lane);
}

// ---------------------------------------------------------------------------
static inline int ceil_div(int a, int b) { return (a + b - 1) / b; }

extern "C" void kernel_launch(void* const* d_in, const int* in_sizes, int n_in,
                              void* d_out, int out_size) {
    const float* features = (const float*)d_in[0];
    const void*  edge_idx = d_in[1];
    const float* W1       = (const float*)d_in[2];
    const float* b1       = (const float*)d_in[3];
    const float* W2       = (const float*)d_in[4];
    const float* b2       = (const float*)d_in[5];
    const float* b3       = (const float*)d_in[6];
    const float* b4       = (const float*)d_in[7];
    const float* head1    = (const float*)d_in[8];

    const int n = in_sizes[0] / IN_DIM;
    const int e = in_sizes[1] / 2;

    float* out = (float*)d_out;
    float* z_out  = out;
    float* h2_out = out + (size_t)n * OUT_DIM;
    float* h4_out = out + (size_t)n * OUT_DIM * 2;

    const int TPB = 256;
    dim3 blk(256);

    static cudaStream_t s1 = nullptr, s2 = nullptr;
    static cudaEvent_t evFork = nullptr, evXh = nullptr, evP = nullptr,
                       evAux = nullptr, evHW = nullptr, evAgg = nullptr,
                       evZ = nullptr;
    if (s1 == nullptr) {
        cudaStreamCreateWithFlags(&s1, cudaStreamNonBlocking);
        cudaStreamCreateWithFlags(&s2, cudaStreamNonBlocking);
        cudaEventCreateWithFlags(&evFork, cudaEventDisableTiming);
        cudaEventCreateWithFlags(&evXh,   cudaEventDisableTiming);
        cudaEventCreateWithFlags(&evP,    cudaEventDisableTiming);
        cudaEventCreateWithFlags(&evAux,  cudaEventDisableTiming);
        cudaEventCreateWithFlags(&evHW,   cudaEventDisableTiming);
        cudaEventCreateWithFlags(&evAgg,  cudaEventDisableTiming);
        cudaEventCreateWithFlags(&evZ,    cudaEventDisableTiming);
    }

    // ---- fork ----
    cudaEventRecord(evFork, 0);
    cudaStreamWaitEvent(s1, evFork, 0);
    cudaStreamWaitEvent(s2, evFork, 0);

    // s2: X -> half
    {
        int total8 = n * IN_DIM / 8;
        k_xh<<<ceil_div(total8, TPB), TPB, 0, s2>>>(features, total8);
    }
    cudaEventRecord(evXh, s2);

    // s1: w21 -> (wait Xh) P -> misc -> hw21
    {
        dim3 grid(IN_DIM / 128, 4);
        k_w21<<<grid, blk, 0, s1>>>(W2, W1);
    }
    cudaStreamWaitEvent(s1, evXh, 0);
    {
        dim3 grid(1, ceil_div(n, 64));   // P = Xh @ W21^T -> g_Th (half)
        k_mma<4, 3, 1, 0, 64><<<grid, blk, 0, s1>>>(n, OUT_DIM, IN_DIM,
                                                    nullptr, nullptr);
    }
    cudaEventRecord(evP, s1);
    k_misc<<<18, 256, 0, s1>>>(W1, W2, b1, b3, head1);
    cudaEventRecord(evAux, s1);
    {
        dim3 grid(IN_DIM / 128, 4);
        k_hw21<<<grid, blk, 0, s1>>>(head1);
    }
    cudaEventRecord(evHW, s1);

    // s0: CSR chain (k_scan zeros g_cnt + barrier counters)
    k_count<<<ceil_div(e, TPB), TPB>>>(edge_idx, e, n);
    k_scan<<<1, 1024>>>(n);
    k_fill<<<ceil_div(e, TPB), TPB>>>(edge_idx, e, n);

    // s0: megakernel aggregation (needs P, u2)
    cudaStreamWaitEvent(0, evP, 0);
    cudaStreamWaitEvent(0, evAux, 0);
    k_megagg<<<AGG_CTAS, blk>>>(h2_out, b2, n);
    cudaEventRecord(evAgg, 0);

    // s1: z = (h2 half) @ head1 -> z_out (parallel with h4)
    cudaStreamWaitEvent(s1, evAgg, 0);
    {
        dim3 grid(1, ceil_div(n, 64));
        k_mma<1, 5, 0, 0, 64><<<grid, blk, 0, s1>>>(n, OUT_DIM, OUT_DIM,
                                                    z_out, nullptr);
    }
    cudaEventRecord(evZ, s1);

    // s0: h4 = R @ HW21 + c(x)u4 + b4 -> h4_out
    cudaStreamWaitEvent(0, evHW, 0);
    {
        dim3 grid(IN_DIM / 128, ceil_div(n, 128));
        k_mma<2, 4, 0, 1, 128><<<grid, blk>>>(n, IN_DIM, OUT_DIM,
                                              h4_out, b4);
    }

    cudaStreamWaitEvent(0, evZ, 0);

    (void)n_in; (void)out_size;
}

// round 17
// speedup vs baseline: 1.2027x; 1.2027x over previous
#include <cuda_runtime.h>
#include <cuda_fp16.h>
#include <cstdint>

// ---------------------------------------------------------------------------
// GAE 4-layer GCN autoencoder: algebraic fusion + fp16 pipeline + fp16 mma.
// R17: revert megakernel (R15 agg structure), keep X-half preconvert on s2,
// parallelized k_misc moved to s2 (off the agg critical path).
// ---------------------------------------------------------------------------

#define N_NODES 20000
#define IN_DIM  1024
#define HID_DIM 512
#define OUT_DIM 128
#define N_EDGES 160000

__device__ alignas(16) __half g_Xh[(size_t)N_NODES * IN_DIM];       // X half
__device__ alignas(16) __half g_Th[(size_t)N_NODES * OUT_DIM];      // P / S2
__device__ alignas(16) __half g_Hh[(size_t)N_NODES * OUT_DIM];      // S1 / R
__device__ alignas(16) __half g_Zh[(size_t)N_NODES * OUT_DIM];      // h2 half copy
__device__ alignas(16) float  g_W21[(size_t)OUT_DIM * IN_DIM];      // fp32 (for hw21)
__device__ alignas(16) __half g_W21h[(size_t)OUT_DIM * IN_DIM];     // [128,1024] n-major
__device__ alignas(16) __half g_HW21th[(size_t)IN_DIM * OUT_DIM];   // [1024,128] n-major
__device__ alignas(16) __half g_Hth[(size_t)OUT_DIM * OUT_DIM];     // head1^T
__device__ alignas(16) float  g_u2[OUT_DIM];
__device__ alignas(16) float  g_u4[IN_DIM];
__device__ float g_dinv[N_NODES];
__device__ float g_sn[N_NODES];
__device__ float g_c[N_NODES];
__device__ int   g_cnt[N_NODES];     // invariant: zero at kernel_launch entry
__device__ int   g_off[N_NODES + 1];
__device__ int   g_cur[N_NODES];
__device__ int2  g_adj[N_EDGES];

// half buffer selectors: 1 g_Th, 2 g_Hh, 3 g_Zh
template <int SEL>
__device__ __forceinline__ const __half* pickhb() {
    if (SEL == 1) return g_Th;
    if (SEL == 2) return g_Hh;
    return g_Zh;
}
template <int SEL>
__device__ __forceinline__ __half* pickhbw() {
    if (SEL == 1) return g_Th;
    if (SEL == 2) return g_Hh;
    return g_Zh;
}
// mma B selectors: 3 g_W21h, 4 g_HW21th, 5 g_Hth
template <int SEL>
__device__ __forceinline__ const __half* pickB() {
    if (SEL == 3) return g_W21h;
    if (SEL == 4) return g_HW21th;
    return g_Hth;
}

__device__ __forceinline__ float4 h4f(uint2 r) {
    __half2 a = *(__half2*)&r.x, b = *(__half2*)&r.y;
    float2 f0 = __half22float2(a), f1 = __half22float2(b);
    return make_float4(f0.x, f0.y, f1.x, f1.y);
}
__device__ __forceinline__ uint2 f4h(float4 v) {
    __half2 a = __floats2half2_rn(v.x, v.y);
    __half2 b = __floats2half2_rn(v.z, v.w);
    uint2 r;
    r.x = *(unsigned*)&a; r.y = *(unsigned*)&b;
    return r;
}

// int64 detection (int64 idx < 2^31 -> odd int32 words zero)
__device__ __forceinline__ int probe64(const int* __restrict__ ei32) {
    return (ei32[1] == 0) & (ei32[3] == 0) & (ei32[5] == 0) &
           (ei32[7] == 0) & (ei32[9] == 0) & (ei32[11] == 0);
}
__device__ __forceinline__ int load_idx64(const void* ei, int is64, int e_cnt,
                                          int row, int e) {
    if (is64) return (int)((const long long*)ei)[(size_t)row * e_cnt + e];
    return ((const int*)ei)[(size_t)row * e_cnt + e];
}

// ---------------------------------------------------------------------------
// X -> half (streaming convert; 8 floats per thread)
// ---------------------------------------------------------------------------
__global__ void k_xh(const float* __restrict__ X, int total8) {
    int i = blockIdx.x * blockDim.x + threadIdx.x;
    if (i < total8) {
        float4 a = ((const float4*)X)[(size_t)i * 2];
        float4 b = ((const float4*)X)[(size_t)i * 2 + 1];
        uint4 o;
        __half2 h;
        h = __floats2half2_rn(a.x, a.y); o.x = *(unsigned*)&h;
        h = __floats2half2_rn(a.z, a.w); o.y = *(unsigned*)&h;
        h = __floats2half2_rn(b.x, b.y); o.z = *(unsigned*)&h;
        h = __floats2half2_rn(b.z, b.w); o.w = *(unsigned*)&h;
        *(uint4*)(g_Xh + (size_t)i * 8) = o;
    }
}

// ---------------------------------------------------------------------------
// CSR: count (g_cnt zero at entry; k_scan restores it)
// ---------------------------------------------------------------------------
__global__ void k_count(const void* __restrict__ ei, int e_cnt, int n) {
    int e = blockIdx.x * blockDim.x + threadIdx.x;
    int is64 = probe64((const int*)ei);
    if (e < e_cnt) {
        int d = load_idx64(ei, is64, e_cnt, 1, e);
        if ((unsigned)d < (unsigned)n) atomicAdd(&g_cnt[d], 1);
    }
}

// ---------------------------------------------------------------------------
// Single-pass scan (+ dinv/sn); re-zeros g_cnt for the next call.
// ---------------------------------------------------------------------------
#define SCAN_CHUNK ((N_NODES + 1023) / 1024)

__global__ __launch_bounds__(1024)
void k_scan(int n) {
    int tid = threadIdx.x;
    int lane = tid & 31, wid = tid >> 5;
    int base = tid * SCAN_CHUNK;
    int vloc[SCAN_CHUNK];
    int s = 0;
#pragma unroll
    for (int j = 0; j < SCAN_CHUNK; j++) {
        int i = base + j;
        int v = (i < n) ? g_cnt[i] : 0;
        vloc[j] = v;
        s += v;
    }
    int x = s;
#pragma unroll
    for (int d = 1; d < 32; d <<= 1) {
        int y = __shfl_up_sync(0xFFFFFFFFu, x, d);
        if (lane >= d) x += y;
    }
    __shared__ int ws[32];
    if (lane == 31) ws[wid] = x;
    __syncthreads();
    if (wid == 0) {
        int w = ws[lane];
#pragma unroll
        for (int d = 1; d < 32; d <<= 1) {
            int y = __shfl_up_sync(0xFFFFFFFFu, w, d);
            if (lane >= d) w += y;
        }
        ws[lane] = w;
    }
    __syncthreads();
    int excl = x - s + ((wid > 0) ? ws[wid - 1] : 0);
    if (tid == 0) g_off[0] = 0;
#pragma unroll
    for (int j = 0; j < SCAN_CHUNK; j++) {
        int i = base + j;
        if (i < n) {
            g_cur[i] = excl;
            excl += vloc[j];
            g_off[i + 1] = excl;
            float r = rsqrtf((float)(vloc[j] + 1));
            g_dinv[i] = r;
            g_sn[i] = r * r;
            g_cnt[i] = 0;   // restore invariant
        }
    }
}

__global__ void k_fill(const void* __restrict__ ei, int e_cnt, int n) {
    int e = blockIdx.x * blockDim.x + threadIdx.x;
    int is64 = probe64((const int*)ei);
    if (e < e_cnt) {
        int s = load_idx64(ei, is64, e_cnt, 0, e);
        int d = load_idx64(ei, is64, e_cnt, 1, e);
        if ((unsigned)s >= (unsigned)n) s = 0;
        if ((unsigned)d >= (unsigned)n) d = 0;
        float w = g_dinv[s] * g_dinv[d];
        int pos = atomicAdd(&g_cur[d], 1);
        g_adj[pos] = make_int2(s, __float_as_int(w));
    }
}

// ---------------------------------------------------------------------------
// misc (parallelized): u4 blocks 0..63 (16 f's each, 16-way k-split),
// u2 block 64, Hth block 65.
// ---------------------------------------------------------------------------
__global__ void k_misc(const float* __restrict__ W1, const float* __restrict__ W2,
                       const float* __restrict__ b1, const float* __restrict__ b3,
                       const float* __restrict__ head1) {
    int b = blockIdx.x;
    __shared__ float red[256];
    if (b < 64) {
        int fl = threadIdx.x & 15;      // 0..15
        int kg = threadIdx.x >> 4;      // 0..15
        int f = b * 16 + fl;
        float s = 0.f;
#pragma unroll 4
        for (int k = kg * 32; k < kg * 32 + 32; k++)
            s += b3[k] * W1[(size_t)k * IN_DIM + f];
        red[threadIdx.x] = s;
        __syncthreads();
        if (threadIdx.x < 16) {
            float t = 0.f;
#pragma unroll
            for (int q = 0; q < 16; q++) t += red[threadIdx.x + q * 16];
            g_u4[b * 16 + threadIdx.x] = t;
        }
    } else if (b == 64) {
        int o = threadIdx.x & 127;
        int kg = threadIdx.x >> 7;      // 0..1
        float s = 0.f;
        for (int k = kg * 256; k < kg * 256 + 256; k++)
            s += W2[(size_t)o * HID_DIM + k] * b1[k];
        red[threadIdx.x] = s;
        __syncthreads();
        if (threadIdx.x < 128)
            g_u2[threadIdx.x] = red[threadIdx.x] + red[128 + threadIdx.x];
    } else {
        for (int idx = threadIdx.x; idx < OUT_DIM * OUT_DIM; idx += 256) {
            int r = idx >> 7, c = idx & 127;
            g_Hth[(size_t)c * OUT_DIM + r] = __float2half(head1[idx]);
        }
    }
}

// ---------------------------------------------------------------------------
// W21 = W2 @ W1 (fp32 FFMA, K=512) -> g_W21 fp32 + g_W21h half.
// grid (IN_DIM/128, 4), BM=32.
// ---------------------------------------------------------------------------
__global__ __launch_bounds__(256)
void k_w21(const float* __restrict__ A, const float* __restrict__ B) {
    __shared__ float As[8][32];
    __shared__ float Bs[8][128];
    const int bx = blockIdx.x;
    const int by = blockIdx.y;
    const int tid = threadIdx.x;
    const int tcol = tid % 16;
    const int trow = tid / 16;

    float acc[2][8];
#pragma unroll
    for (int i = 0; i < 2; i++)
#pragma unroll
        for (int j = 0; j < 8; j++) acc[i][j] = 0.0f;

    for (int k0 = 0; k0 < HID_DIM; k0 += 8) {
        if (tid < 64) {
            int aRow = tid >> 1;
            int aCol = (tid & 1) << 2;
            int m = by * 32 + aRow;
            float4 av = *(const float4*)(A + (size_t)m * HID_DIM + k0 + aCol);
            As[aCol + 0][aRow] = av.x;
            As[aCol + 1][aRow] = av.y;
            As[aCol + 2][aRow] = av.z;
            As[aCol + 3][aRow] = av.w;
        }
        {
            int kk = tid >> 5;
            int nn = (tid & 31) << 2;
            float4 bv = *(const float4*)(B + (size_t)(k0 + kk) * IN_DIM + bx * 128 + nn);
            *(float4*)&Bs[kk][nn] = bv;
        }
        __syncthreads();
#pragma unroll
        for (int k = 0; k < 8; k++) {
            float ra[2], rb[8];
#pragma unroll
            for (int i = 0; i < 2; i++) ra[i] = As[k][trow * 2 + i];
#pragma unroll
            for (int j = 0; j < 8; j++) rb[j] = Bs[k][tcol * 8 + j];
#pragma unroll
            for (int i = 0; i < 2; i++)
#pragma unroll
                for (int j = 0; j < 8; j++) acc[i][j] += ra[i] * rb[j];
        }
        __syncthreads();
    }
#pragma unroll
    for (int i = 0; i < 2; i++) {
        int m = by * 32 + trow * 2 + i;
#pragma unroll
        for (int j = 0; j < 8; j++) {
            int col = bx * 128 + tcol * 8 + j;
            g_W21[(size_t)m * IN_DIM + col]  = acc[i][j];
            g_W21h[(size_t)m * IN_DIM + col] = __float2half(acc[i][j]);
        }
    }
}

// ---------------------------------------------------------------------------
// HW21 = head1 @ W21 (fp32 FFMA, K=128) -> g_HW21th half transposed.
// grid (IN_DIM/128, 4), BM=32.
// ---------------------------------------------------------------------------
__global__ __launch_bounds__(256)
void k_hw21(const float* __restrict__ head1) {
    __shared__ float As[8][32];
    __shared__ float Bs[8][128];
    const int bx = blockIdx.x;
    const int by = blockIdx.y;
    const int tid = threadIdx.x;
    const int tcol = tid % 16;
    const int trow = tid / 16;

    float acc[2][8];
#pragma unroll
    for (int i = 0; i < 2; i++)
#pragma unroll
        for (int j = 0; j < 8; j++) acc[i][j] = 0.0f;

    for (int k0 = 0; k0 < OUT_DIM; k0 += 8) {
        if (tid < 64) {
            int aRow = tid >> 1;
            int aCol = (tid & 1) << 2;
            int m = by * 32 + aRow;
            float4 av = *(const float4*)(head1 + (size_t)m * OUT_DIM + k0 + aCol);
            As[aCol + 0][aRow] = av.x;
            As[aCol + 1][aRow] = av.y;
            As[aCol + 2][aRow] = av.z;
            As[aCol + 3][aRow] = av.w;
        }
        {
            int kk = tid >> 5;
            int nn = (tid & 31) << 2;
            float4 bv = *(const float4*)(g_W21 + (size_t)(k0 + kk) * IN_DIM + bx * 128 + nn);
            *(float4*)&Bs[kk][nn] = bv;
        }
        __syncthreads();
#pragma unroll
        for (int k = 0; k < 8; k++) {
            float ra[2], rb[8];
#pragma unroll
            for (int i = 0; i < 2; i++) ra[i] = As[k][trow * 2 + i];
#pragma unroll
            for (int j = 0; j < 8; j++) rb[j] = Bs[k][tcol * 8 + j];
#pragma unroll
            for (int i = 0; i < 2; i++)
#pragma unroll
                for (int j = 0; j < 8; j++) acc[i][j] += ra[i] * rb[j];
        }
        __syncthreads();
    }
#pragma unroll
    for (int i = 0; i < 2; i++) {
        int m = by * 32 + trow * 2 + i;
#pragma unroll
        for (int j = 0; j < 8; j++) {
            int col = bx * 128 + tcol * 8 + j;
            g_HW21th[(size_t)col * OUT_DIM + m] = __float2half(acc[i][j]);
        }
    }
}

// ---------------------------------------------------------------------------
// fp16 tensor-core GEMM (TN form), m16n8k16, register-prefetch pipelined.
//   AMODE: 1 = g_Zh, 2 = g_Hh, 4 = g_Xh (all half A).
//   CH: 1 -> C = g_Th (half); 0 -> C = Cext fp32.
// ---------------------------------------------------------------------------
template <int AMODE, int BSEL, int CH, int CORR4, int BMv>
__global__ __launch_bounds__(256)
void k_mma(int M, int Nn, int K,
           float* __restrict__ Cext,
           const float* __restrict__ bias) {
    constexpr int MT = BMv / 32;
    constexpr int ARH = (BMv + 63) / 64;
    const __half* B = pickB<BSEL>();
    const __half* Ah = (AMODE == 1) ? g_Zh : (AMODE == 2) ? g_Hh : g_Xh;

    __shared__ __half As[BMv][40];
    __shared__ __half Bs[128][40];

    const int tid  = threadIdx.x;
    const int lane = tid & 31;
    const int wid  = tid >> 5;
    const int g    = lane >> 2;
    const int t    = lane & 3;
    const int wm   = (wid & 1) * (BMv / 2);
    const int wn   = (wid >> 1) * 32;
    const int bx   = blockIdx.x;
    const int by   = blockIdx.y;

    uint4 arh[ARH];
    uint4 br4[2];

    auto loadA = [&](int k0) {
#pragma unroll
        for (int i = 0; i < ARH; i++) {
            int u  = tid + i * 256;
            int m  = u >> 2;
            int kq = (u & 3) << 3;
            int gm = by * BMv + m;
            arh[i] = (gm < M) ? *(const uint4*)(Ah + (size_t)gm * K + k0 + kq)
                              : make_uint4(0, 0, 0, 0);
        }
    };
    auto loadB = [&](int k0) {
#pragma unroll
        for (int i = 0; i < 2; i++) {
            int f4 = tid + i * 256;
            int nn = f4 >> 2;
            int kq = (f4 & 3) << 3;
            br4[i] = *(const uint4*)(B + (size_t)(bx * 128 + nn) * K + k0 + kq);
        }
    };
    auto storeA = [&]() {
#pragma unroll
        for (int i = 0; i < ARH; i++) {
            int u  = tid + i * 256;
            int m  = u >> 2;
            int kq = (u & 3) << 3;
            *(uint4*)&As[m][kq] = arh[i];
        }
    };
    auto storeB = [&]() {
#pragma unroll
        for (int i = 0; i < 2; i++) {
            int f4 = tid + i * 256;
            int nn = f4 >> 2;
            int kq = (f4 & 3) << 3;
            *(uint4*)&Bs[nn][kq] = br4[i];
        }
    };

    float c[MT][4][4];
#pragma unroll
    for (int i = 0; i < MT; i++)
#pragma unroll
        for (int j = 0; j < 4; j++)
#pragma unroll
            for (int r = 0; r < 4; r++) c[i][j][r] = 0.0f;

    const int nt = K / 32;
    loadA(0); loadB(0);
    storeA(); storeB();
    __syncthreads();

    for (int it = 0; it < nt; it++) {
        if (it + 1 < nt) { loadA((it + 1) * 32); loadB((it + 1) * 32); }

#pragma unroll
        for (int ks = 0; ks < 2; ks++) {
            unsigned a[MT][4], b[4][2];
            int kb = ks * 16 + 2 * t;
#pragma unroll
            for (int i = 0; i < MT; i++) {
                int mr = wm + i * 16 + g;
                a[i][0] = *(const unsigned*)&As[mr    ][kb    ];
                a[i][1] = *(const unsigned*)&As[mr + 8][kb    ];
                a[i][2] = *(const unsigned*)&As[mr    ][kb + 8];
                a[i][3] = *(const unsigned*)&As[mr + 8][kb + 8];
            }
#pragma unroll
            for (int j = 0; j < 4; j++) {
                int nr = wn + j * 8 + g;
                b[j][0] = *(const unsigned*)&Bs[nr][kb    ];
                b[j][1] = *(const unsigned*)&Bs[nr][kb + 8];
            }
#pragma unroll
            for (int i = 0; i < MT; i++)
#pragma unroll
                for (int j = 0; j < 4; j++) {
                    asm volatile(
                        "mma.sync.aligned.m16n8k16.row.col.f32.f16.f16.f32 "
                        "{%0,%1,%2,%3}, {%4,%5,%6,%7}, {%8,%9}, {%0,%1,%2,%3};"
                        : "+f"(c[i][j][0]), "+f"(c[i][j][1]),
                          "+f"(c[i][j][2]), "+f"(c[i][j][3])
                        : "r"(a[i][0]), "r"(a[i][1]), "r"(a[i][2]), "r"(a[i][3]),
                          "r"(b[j][0]), "r"(b[j][1]));
                }
        }
        __syncthreads();
        if (it + 1 < nt) {
            storeA(); storeB();
            __syncthreads();
        }
    }

#pragma unroll
    for (int j = 0; j < 4; j++) {
        int cn = bx * 128 + wn + j * 8 + t * 2;
        float e0 = bias ? bias[cn]     : 0.0f;
        float e1 = bias ? bias[cn + 1] : 0.0f;
        float u40 = CORR4 ? g_u4[cn]     : 0.0f;
        float u41 = CORR4 ? g_u4[cn + 1] : 0.0f;
#pragma unroll
        for (int i = 0; i < MT; i++) {
            int r0 = by * BMv + wm + i * 16 + g;
            if (r0 < M) {
                float a0 = c[i][j][0] + e0, a1 = c[i][j][1] + e1;
                if (CORR4) { float ci = g_c[r0]; a0 += ci * u40; a1 += ci * u41; }
                if (CH) {
                    __half2 h = __floats2half2_rn(a0, a1);
                    *(__half2*)(g_Th + (size_t)r0 * Nn + cn) = h;
                } else {
                    *(float2*)(Cext + (size_t)r0 * Nn + cn) = make_float2(a0, a1);
                }
            }
            int r1 = r0 + 8;
            if (r1 < M) {
                float a2 = c[i][j][2] + e0, a3 = c[i][j][3] + e1;
                if (CORR4) { float ci = g_c[r1]; a2 += ci * u40; a3 += ci * u41; }
                if (CH) {
                    __half2 h = __floats2half2_rn(a2, a3);
                    *(__half2*)(g_Th + (size_t)r1 * Nn + cn) = h;
                } else {
                    *(float2*)(Cext + (size_t)r1 * Nn + cn) = make_float2(a2, a3);
                }
            }
        }
    }
}

// ---------------------------------------------------------------------------
// Aggregation (warp-per-node CSR gather) over HALF sources, fp32 accumulate.
// MLP-8 unrolled edge loop.
// ---------------------------------------------------------------------------
template <int SMODE, int DMODE, int CORR, int WRC>
__global__ __launch_bounds__(256)
void k_agg(float* __restrict__ Dext,
           const float* __restrict__ b,
           int n) {
    int gw = (blockIdx.x * 256 + threadIdx.x) >> 5;
    if (gw >= n) return;
    int lane = threadIdx.x & 31;
    const __half* S = pickhb<SMODE>();

    int beg = g_off[gw];
    int end = g_off[gw + 1];
    float sn = g_sn[gw];
    int lo = lane * 4;
    float4 v = h4f(*(const uint2*)(S + (size_t)gw * OUT_DIM + lo));
    float4 acc = make_float4(sn * v.x, sn * v.y, sn * v.z, sn * v.w);
    float cacc = sn;

    int p = beg;
    for (; p + 8 <= end; p += 8) {
        int2  ee[8];
        uint2 uu[8];
#pragma unroll
        for (int q = 0; q < 8; q++) ee[q] = g_adj[p + q];
#pragma unroll
        for (int q = 0; q < 8; q++)
            uu[q] = *(const uint2*)(S + (size_t)ee[q].x * OUT_DIM + lo);
#pragma unroll
        for (int q = 0; q < 8; q++) {
            float w = __int_as_float(ee[q].y);
            if (WRC) cacc += w;
            float4 u = h4f(uu[q]);
            acc.x += w * u.x; acc.y += w * u.y; acc.z += w * u.z; acc.w += w * u.w;
        }
    }
    for (; p + 4 <= end; p += 4) {
        int2  ee[4];
        uint2 uu[4];
#pragma unroll
        for (int q = 0; q < 4; q++) ee[q] = g_adj[p + q];
#pragma unroll
        for (int q = 0; q < 4; q++)
            uu[q] = *(const uint2*)(S + (size_t)ee[q].x * OUT_DIM + lo);
#pragma unroll
        for (int q = 0; q < 4; q++) {
            float w = __int_as_float(ee[q].y);
            if (WRC) cacc += w;
            float4 u = h4f(uu[q]);
            acc.x += w * u.x; acc.y += w * u.y; acc.z += w * u.z; acc.w += w * u.w;
        }
    }
    for (; p < end; p++) {
        int2 pr = g_adj[p];
        float w = __int_as_float(pr.y);
        if (WRC) cacc += w;
        float4 u = h4f(*(const uint2*)(S + (size_t)pr.x * OUT_DIM + lo));
        acc.x += w * u.x; acc.y += w * u.y; acc.z += w * u.z; acc.w += w * u.w;
    }

    if (WRC && lane == 0) g_c[gw] = cacc;

    if (CORR) {
        float ci = g_c[gw];
        acc.x += ci * g_u2[lo + 0] + b[lo + 0];
        acc.y += ci * g_u2[lo + 1] + b[lo + 1];
        acc.z += ci * g_u2[lo + 2] + b[lo + 2];
        acc.w += ci * g_u2[lo + 3] + b[lo + 3];
    }

    if (DMODE == 0) {
        *(float4*)(Dext + (size_t)gw * OUT_DIM + lo) = acc;
        *(uint2*)(g_Zh + (size_t)gw * OUT_DIM + lo) = f4h(acc);
    } else {
        __half* D = pickhbw<DMODE>();
        *(uint2*)(D + (size_t)gw * OUT_DIM + lo) = f4h(acc);
    }
}

// ---------------------------------------------------------------------------
static inline int ceil_div(int a, int b) { return (a + b - 1) / b; }

extern "C" void kernel_launch(void* const* d_in, const int* in_sizes, int n_in,
                              void* d_out, int out_size) {
    const float* features = (const float*)d_in[0];
    const void*  edge_idx = d_in[1];
    const float* W1       = (const float*)d_in[2];
    const float* b1       = (const float*)d_in[3];
    const float* W2       = (const float*)d_in[4];
    const float* b2       = (const float*)d_in[5];
    const float* b3       = (const float*)d_in[6];
    const float* b4       = (const float*)d_in[7];
    const float* head1    = (const float*)d_in[8];

    const int n = in_sizes[0] / IN_DIM;
    const int e = in_sizes[1] / 2;

    float* out = (float*)d_out;
    float* z_out  = out;
    float* h2_out = out + (size_t)n * OUT_DIM;
    float* h4_out = out + (size_t)n * OUT_DIM * 2;

    const int TPB = 256;
    dim3 blk(256);
    int aggb = ceil_div(n * 32, TPB);

    static cudaStream_t s1 = nullptr, s2 = nullptr;
    static cudaEvent_t evFork = nullptr, evXh = nullptr, evP = nullptr,
                       evAux = nullptr, evHW = nullptr, evH2 = nullptr,
                       evZ = nullptr;
    if (s1 == nullptr) {
        cudaStreamCreateWithFlags(&s1, cudaStreamNonBlocking);
        cudaStreamCreateWithFlags(&s2, cudaStreamNonBlocking);
        cudaEventCreateWithFlags(&evFork, cudaEventDisableTiming);
        cudaEventCreateWithFlags(&evXh,   cudaEventDisableTiming);
        cudaEventCreateWithFlags(&evP,    cudaEventDisableTiming);
        cudaEventCreateWithFlags(&evAux,  cudaEventDisableTiming);
        cudaEventCreateWithFlags(&evHW,   cudaEventDisableTiming);
        cudaEventCreateWithFlags(&evH2,   cudaEventDisableTiming);
        cudaEventCreateWithFlags(&evZ,    cudaEventDisableTiming);
    }

    // ---- fork ----
    cudaEventRecord(evFork, 0);
    cudaStreamWaitEvent(s1, evFork, 0);
    cudaStreamWaitEvent(s2, evFork, 0);

    // s2: X -> half, then misc (both independent of edges / W21)
    {
        int total8 = n * IN_DIM / 8;
        k_xh<<<ceil_div(total8, TPB), TPB, 0, s2>>>(features, total8);
    }
    cudaEventRecord(evXh, s2);
    k_misc<<<66, 256, 0, s2>>>(W1, W2, b1, b3, head1);
    cudaEventRecord(evAux, s2);

    // s1: w21 -> (wait Xh) P -> hw21
    {
        dim3 grid(IN_DIM / 128, 4);
        k_w21<<<grid, blk, 0, s1>>>(W2, W1);
    }
    cudaStreamWaitEvent(s1, evXh, 0);
    {
        dim3 grid(1, ceil_div(n, 64));   // P = Xh @ W21^T -> g_Th (half)
        k_mma<4, 3, 1, 0, 64><<<grid, blk, 0, s1>>>(n, OUT_DIM, IN_DIM,
                                                    nullptr, nullptr);
    }
    cudaEventRecord(evP, s1);
    {
        dim3 grid(IN_DIM / 128, 4);
        k_hw21<<<grid, blk, 0, s1>>>(head1);
    }
    cudaEventRecord(evHW, s1);

    // s0: CSR chain
    k_count<<<ceil_div(e, TPB), TPB>>>(edge_idx, e, n);
    k_scan<<<1, 1024>>>(n);
    k_fill<<<ceil_div(e, TPB), TPB>>>(edge_idx, e, n);

    cudaStreamWaitEvent(0, evP, 0);

    // ---- S1 = Ahat P -> g_Hh (computes c) ----
    k_agg<1, 2, 0, 1><<<aggb, blk>>>(nullptr, nullptr, n);

    // ---- h2 = Ahat S1 + c(x)u2 + b2 -> h2_out (+half copy g_Zh) ----
    cudaStreamWaitEvent(0, evAux, 0);
    k_agg<2, 0, 1, 0><<<aggb, blk>>>(h2_out, b2, n);
    cudaEventRecord(evH2, 0);

    // s1: z = (h2 half) @ head1 -> z_out (parallel with aggs below)
    cudaStreamWaitEvent(s1, evH2, 0);
    {
        dim3 grid(1, ceil_div(n, 64));
        k_mma<1, 5, 0, 0, 64><<<grid, blk, 0, s1>>>(n, OUT_DIM, OUT_DIM,
                                                    z_out, nullptr);
    }
    cudaEventRecord(evZ, s1);

    // ---- S2 = Ahat h2 -> g_Th ; R = Ahat S2 -> g_Hh ----
    k_agg<3, 1, 0, 0><<<aggb, blk>>>(nullptr, nullptr, n);
    k_agg<1, 2, 0, 0><<<aggb, blk>>>(nullptr, nullptr, n);

    // ---- h4 = R @ HW21 + c(x)u4 + b4 -> h4_out ----
    cudaStreamWaitEvent(0, evHW, 0);
    {
        dim3 grid(IN_DIM / 128, ceil_div(n, 128));
        k_mma<2, 4, 0, 1, 128><<<grid, blk>>>(n, IN_DIM, OUT_DIM,
                                              h4_out, b4);
    }

    cudaStreamWaitEvent(0, evZ, 0);

    (void)n_in; (void)out_size;
}